// round 1
// baseline (speedup 1.0000x reference)
#include <cuda_runtime.h>
#include <cuda_bf16.h>

// TopDownProjector: for each column [b,c,y,x,:] (D=256 contiguous floats),
// scan from depth index D-1 downward, find first non-zero voxel.
//   out[0 .. N)   = height_field (depth index of hit, 0 if empty), as float
//   out[N .. 2N)  = seg_map (voxel value at hit, 0 if empty)
//
// Labels uniform in [0,9) -> voxel zero with p=1/9; a float4 of the top 16B
// resolves 99.985% of columns, so expected traffic is ~1 sector/column.

static constexpr int D = 256;

__global__ void topdown_kernel(const float* __restrict__ volume,
                               float* __restrict__ height,
                               float* __restrict__ seg,
                               int n_cols) {
    int col = blockIdx.x * blockDim.x + threadIdx.x;
    if (col >= n_cols) return;

    const float* colp = volume + (size_t)col * D;

    float hit_idx = 0.0f;
    float hit_val = 0.0f;

    // Descend from the top in 16-byte steps. Base offsets are 16B-aligned.
    #pragma unroll 4
    for (int base = D - 4; base >= 0; base -= 4) {
        float4 v = *reinterpret_cast<const float4*>(colp + base);
        if (v.w != 0.0f) { hit_idx = (float)(base + 3); hit_val = v.w; break; }
        if (v.z != 0.0f) { hit_idx = (float)(base + 2); hit_val = v.z; break; }
        if (v.y != 0.0f) { hit_idx = (float)(base + 1); hit_val = v.y; break; }
        if (v.x != 0.0f) { hit_idx = (float)(base + 0); hit_val = v.x; break; }
    }

    height[col] = hit_idx;
    seg[col]    = hit_val;
}

extern "C" void kernel_launch(void* const* d_in, const int* in_sizes, int n_in,
                              void* d_out, int out_size) {
    const float* volume = (const float*)d_in[0];
    float* out = (float*)d_out;

    int n_cols = in_sizes[0] / D;          // 524288 for [2,1,512,512,256]
    float* height = out;                   // first output, flattened
    float* seg    = out + n_cols;          // second output

    int threads = 256;
    int blocks = (n_cols + threads - 1) / threads;
    topdown_kernel<<<blocks, threads>>>(volume, height, seg, n_cols);
}

// round 2
// speedup vs baseline: 1.0627x; 1.0627x over previous
#include <cuda_runtime.h>
#include <cuda_bf16.h>

// TopDownProjector: for each column [b,c,y,x,:] (D=256 contiguous floats),
// scan from depth index D-1 downward, find first non-zero voxel.
//   out[0 .. N)   = height_field (depth index of hit, 0 if empty), as float
//   out[N .. 2N)  = seg_map (voxel value at hit, 0 if empty)
//
// Labels uniform in [0,9): a float4 of the top 16B resolves a column with
// p = 1-(1/9)^4 ~ 99.985%. Each thread handles 4 consecutive columns with
// 4 independent top loads (MLP=4), then float4-coalesced stores.

static constexpr int D = 256;

// Resolve one column given its already-loaded top float4 (base = D-4).
// Returns {hit_idx, hit_val}. Falls into a descent loop only when the top
// 4 voxels are all zero (~1/6561 of columns).
__device__ __forceinline__ float2 resolve_col(const float* __restrict__ colp,
                                              float4 v) {
    int base = D - 4;
    for (;;) {
        if (v.w != 0.0f) return make_float2((float)(base + 3), v.w);
        if (v.z != 0.0f) return make_float2((float)(base + 2), v.z);
        if (v.y != 0.0f) return make_float2((float)(base + 1), v.y);
        if (v.x != 0.0f) return make_float2((float)(base + 0), v.x);
        base -= 4;
        if (base < 0) return make_float2(0.0f, 0.0f);
        v = *reinterpret_cast<const float4*>(colp + base);
    }
}

__global__ void topdown_kernel4(const float* __restrict__ volume,
                                float4* __restrict__ height4,
                                float4* __restrict__ seg4,
                                int n_quads) {
    int q = blockIdx.x * blockDim.x + threadIdx.x;
    if (q >= n_quads) return;

    const float* p0 = volume + ((size_t)q * 4 + 0) * D;
    const float* p1 = volume + ((size_t)q * 4 + 1) * D;
    const float* p2 = volume + ((size_t)q * 4 + 2) * D;
    const float* p3 = volume + ((size_t)q * 4 + 3) * D;

    // Four independent top loads issued back-to-back (MLP=4).
    float4 v0 = *reinterpret_cast<const float4*>(p0 + (D - 4));
    float4 v1 = *reinterpret_cast<const float4*>(p1 + (D - 4));
    float4 v2 = *reinterpret_cast<const float4*>(p2 + (D - 4));
    float4 v3 = *reinterpret_cast<const float4*>(p3 + (D - 4));

    float2 r0 = resolve_col(p0, v0);
    float2 r1 = resolve_col(p1, v1);
    float2 r2 = resolve_col(p2, v2);
    float2 r3 = resolve_col(p3, v3);

    height4[q] = make_float4(r0.x, r1.x, r2.x, r3.x);
    seg4[q]    = make_float4(r0.y, r1.y, r2.y, r3.y);
}

extern "C" void kernel_launch(void* const* d_in, const int* in_sizes, int n_in,
                              void* d_out, int out_size) {
    const float* volume = (const float*)d_in[0];
    float* out = (float*)d_out;

    int n_cols  = in_sizes[0] / D;     // 524288 for [2,1,512,512,256]
    int n_quads = n_cols / 4;          // n_cols divisible by 4 here

    float4* height4 = (float4*)out;                      // [0, N) as float4
    float4* seg4    = (float4*)(out + n_cols);           // [N, 2N) as float4

    int threads = 256;
    int blocks = (n_quads + threads - 1) / threads;      // 512 blocks: 1 wave
    topdown_kernel4<<<blocks, threads>>>(volume, height4, seg4, n_quads);
}